// round 1
// baseline (speedup 1.0000x reference)
#include <cuda_runtime.h>
#include <cstdint>

typedef unsigned long long ull;

// ---------------------------------------------------------------------------
// Packed f32x2 FMA (Blackwell): d.lo += a.lo*b.lo ; d.hi += a.hi*b.hi
// ---------------------------------------------------------------------------
__device__ __forceinline__ void ffma2(ull& d, ull a, ull b) {
    asm volatile("fma.rn.f32x2 %0, %1, %2, %0;" : "+l"(d) : "l"(a), "l"(b));
}

__device__ __forceinline__ float2 u2f2(ull v) {
    float2 f;
    f.x = __uint_as_float((unsigned)(v & 0xffffffffull));
    f.y = __uint_as_float((unsigned)(v >> 32));
    return f;
}

// 16B global load, L2-only (.cg) — used for cross-SM-coherent h reads.
__device__ __forceinline__ ulonglong2 ldcg_v2u64(const float* p) {
    ulonglong2 v;
    asm volatile("ld.global.cg.v2.u64 {%0, %1}, [%2];"
                 : "=l"(v.x), "=l"(v.y) : "l"(p));
    return v;
}

// ---------------------------------------------------------------------------
// Kernel 1: C[m, n] = sum_k A[m,k] * Bm[k,n] + Cst[m / T, n]
//   A: (M=B*T, K=1024) = x, Bm: (K, N=1024) = kernel, Cst: (B, N) = const
//   Writes xw directly into d_out.
// 128x128 tile, BK=8, 256 threads, 8x8 per thread, f32x2 math.
// A stored in smem pre-duplicated into both f32x2 lanes (no pack in inner loop).
// ---------------------------------------------------------------------------
#define G_BM 128
#define G_BN 128
#define G_BK 8

__global__ void __launch_bounds__(256) gemm_xw_kernel(
    const float* __restrict__ A,
    const float* __restrict__ Bm,
    const float* __restrict__ Cst,
    float* __restrict__ C,
    int M, int N, int K, int T)
{
    __shared__ ull   As2[G_BK][G_BM];  // duplicated-pair floats (8 KB)
    __shared__ float Bs[G_BK][G_BN];   // 4 KB

    const int tid  = threadIdx.x;
    const int tcol = tid & 15;   // N direction (x8)
    const int trow = tid >> 4;   // M direction (x8)

    const size_t mBase = (size_t)blockIdx.y * G_BM;
    const int    nBase = blockIdx.x * G_BN;

    const float* Ag = A + mBase * (size_t)K;
    const float* Bg = Bm + nBase;

    const int arow = tid >> 1;          // 0..127
    const int acol = (tid & 1) * 4;     // 0 or 4
    const int brow = tid >> 6;          // 0..3  (4 rows of 2 tiles? no: see below)
    // B tile 8x128 = 1024 floats / 256 threads = 4 floats each:
    const int brow8 = tid >> 5;         // 0..7
    const int bcol  = (tid & 31) * 4;   // 0..124
    (void)brow;

    ull acc[8][4];
#pragma unroll
    for (int i = 0; i < 8; i++)
#pragma unroll
        for (int jp = 0; jp < 4; jp++) acc[i][jp] = 0ull;

    for (int k0 = 0; k0 < K; k0 += G_BK) {
        float4 a4 = *(const float4*)(Ag + (size_t)arow * K + k0 + acol);
        {
            ull d;
            d = (ull)__float_as_uint(a4.x); As2[acol + 0][arow] = d | (d << 32);
            d = (ull)__float_as_uint(a4.y); As2[acol + 1][arow] = d | (d << 32);
            d = (ull)__float_as_uint(a4.z); As2[acol + 2][arow] = d | (d << 32);
            d = (ull)__float_as_uint(a4.w); As2[acol + 3][arow] = d | (d << 32);
        }
        float4 b4 = *(const float4*)(Bg + (size_t)(k0 + brow8) * N + bcol);
        *(float4*)&Bs[brow8][bcol] = b4;
        __syncthreads();

#pragma unroll
        for (int kk = 0; kk < G_BK; kk++) {
            ull a[8];
            {
                ulonglong2 t0 = *(const ulonglong2*)&As2[kk][trow * 8 + 0];
                ulonglong2 t1 = *(const ulonglong2*)&As2[kk][trow * 8 + 2];
                ulonglong2 t2 = *(const ulonglong2*)&As2[kk][trow * 8 + 4];
                ulonglong2 t3 = *(const ulonglong2*)&As2[kk][trow * 8 + 6];
                a[0] = t0.x; a[1] = t0.y; a[2] = t1.x; a[3] = t1.y;
                a[4] = t2.x; a[5] = t2.y; a[6] = t3.x; a[7] = t3.y;
            }
            ull b[4];
            {
                ulonglong2 u0 = *(const ulonglong2*)&Bs[kk][tcol * 8 + 0];
                ulonglong2 u1 = *(const ulonglong2*)&Bs[kk][tcol * 8 + 4];
                b[0] = u0.x; b[1] = u0.y; b[2] = u1.x; b[3] = u1.y;
            }
#pragma unroll
            for (int i = 0; i < 8; i++)
#pragma unroll
                for (int jp = 0; jp < 4; jp++)
                    ffma2(acc[i][jp], a[i], b[jp]);
        }
        __syncthreads();
    }

    // Epilogue: add per-batch const and store. BM divides T, so one batch per tile.
    const int bidx = (int)(mBase / (size_t)T);
    const float* cb0 = Cst + (size_t)bidx * N + nBase + tcol * 8;
#pragma unroll
    for (int i = 0; i < 8; i++) {
        size_t row = mBase + (size_t)(trow * 8 + i);
        float* cp = C + row * (size_t)N + nBase + tcol * 8;
        float4 c0 = *(const float4*)cb0;
        float4 c1 = *(const float4*)(cb0 + 4);
        float2 q0 = u2f2(acc[i][0]);
        float2 q1 = u2f2(acc[i][1]);
        float2 q2 = u2f2(acc[i][2]);
        float2 q3 = u2f2(acc[i][3]);
        c0.x += q0.x; c0.y += q0.y; c0.z += q1.x; c0.w += q1.y;
        c1.x += q2.x; c1.y += q2.y; c1.z += q3.x; c1.w += q3.y;
        *(float4*)cp       = c0;
        *(float4*)(cp + 4) = c1;
    }
}

// ---------------------------------------------------------------------------
// Grid barrier state: one counter per timestep, zeroed by a prologue kernel
// each replay (no reset races, graph-capture safe).
// ---------------------------------------------------------------------------
#define MAX_T 2048
__device__ volatile unsigned g_bar[MAX_T];

__global__ void __launch_bounds__(256) bar_reset_kernel() {
    int i = blockIdx.x * blockDim.x + threadIdx.x;
    if (i < MAX_T) *(unsigned*)&g_bar[i] = 0u;
}

// ---------------------------------------------------------------------------
// Kernel 2: in-place recurrent scan.
//   out[b][t][:] += out[b][t-1][:] @ R   (out[t-1] is the finalized h_{t-1})
// 128 persistent CTAs, CTA c owns columns [8c, 8c+8). R column-slice lives in
// smem transposed (pad 1028 -> conflict-free LDS.128). Lane (b,j) accumulates
// one output via f32x2 over k. h loads are ld.global.cg (coherent across SMs).
// ---------------------------------------------------------------------------
#define SCAN_P 128
#define NC 8
#define RPAD 1028

__global__ void __launch_bounds__(256) scan_kernel(
    const float* __restrict__ h0,   // (B, U)
    const float* __restrict__ R,    // (U, U)
    float* __restrict__ out,        // (B, T, U), xw preloaded
    int T, int U)
{
    __shared__ float RsT[NC][RPAD];

    const int cta  = blockIdx.x;
    const int col0 = cta * NC;
    const int tid  = threadIdx.x;

    // Load R[:, col0:col0+8] transposed into smem (one time).
    for (int idx = tid; idx < NC * 1024; idx += 256) {
        int j = idx & (NC - 1);
        int k = idx >> 3;
        RsT[j][k] = R[(size_t)k * U + col0 + j];
    }
    __syncthreads();

    const int lane = tid & 31;
    const int warp = tid >> 5;
    const int j = lane & 7;              // column within CTA slice
    const int b = warp * 4 + (lane >> 3);// batch row 0..31

    const float* Rrow = &RsT[j][0];
    float* outRow = out + (size_t)b * T * U;
    float* po     = outRow + col0 + j;

    const float* hrow = h0 + (size_t)b * U;
    const unsigned P = gridDim.x;

    for (int t = 0; t < T; t++) {
        ull a0 = 0ull, a1 = 0ull, a2 = 0ull, a3 = 0ull;
#pragma unroll 4
        for (int k = 0; k < 1024; k += 8) {
            ulonglong2 h01 = ldcg_v2u64(hrow + k);       // h[k..k+3]
            ulonglong2 h23 = ldcg_v2u64(hrow + k + 4);   // h[k+4..k+7]
            ulonglong2 r01 = *(const ulonglong2*)(Rrow + k);
            ulonglong2 r23 = *(const ulonglong2*)(Rrow + k + 4);
            ffma2(a0, h01.x, r01.x);
            ffma2(a1, h01.y, r01.y);
            ffma2(a2, h23.x, r23.x);
            ffma2(a3, h23.y, r23.y);
        }
        float2 f0 = u2f2(a0), f1 = u2f2(a1), f2 = u2f2(a2), f3 = u2f2(a3);
        float sum = ((f0.x + f0.y) + (f1.x + f1.y)) +
                    ((f2.x + f2.y) + (f3.x + f3.y));

        float* pt = po + (size_t)t * U;
        *pt = *pt + sum;                  // xw_t + h_{t-1}@R

        hrow = outRow + (size_t)t * U;    // next step reads finalized h_t

        if (t + 1 < T) {
            __threadfence();              // publish our stores before arrival
            __syncthreads();
            if (tid == 0) {
                unsigned arrived = atomicAdd((unsigned*)&g_bar[t], 1u) + 1u;
                if (arrived < P) {
                    while (g_bar[t] < P) { }
                }
                __threadfence();          // acquire
            }
            __syncthreads();
        }
    }
}

// ---------------------------------------------------------------------------
// Launch: inputs are x, h0, const, kernel, recurrent_kernel (metadata order).
// ---------------------------------------------------------------------------
extern "C" void kernel_launch(void* const* d_in, const int* in_sizes, int n_in,
                              void* d_out, int out_size)
{
    const float* x    = (const float*)d_in[0];
    const float* h0   = (const float*)d_in[1];
    const float* cst  = (const float*)d_in[2];
    const float* kern = (const float*)d_in[3];
    const float* rker = (const float*)d_in[4];
    float* out = (float*)d_out;

    const int U = 1024;
    const int D = 1024;
    const int B = in_sizes[2] / U;                 // const is (B,U) -> 32
    const int T = in_sizes[0] / (B * D);           // x is (B,T,D)   -> 2048
    const int M = B * T;

    // 1) reset barrier counters (graph-replay safe)
    bar_reset_kernel<<<(MAX_T + 255) / 256, 256>>>();

    // 2) xw = x @ kernel + const   (written into d_out)
    dim3 g1(U / G_BN, M / G_BM);
    gemm_xw_kernel<<<g1, 256>>>(x, kern, cst, out, M, U, D, T);

    // 3) in-place recurrent scan
    scan_kernel<<<SCAN_P, 256>>>(h0, rker, out, T, U);
}

// round 2
// speedup vs baseline: 3.5016x; 3.5016x over previous
#include <cuda_runtime.h>
#include <cstdint>

typedef unsigned long long ull;
typedef long long ll;

// ---------------------------------------------------------------------------
// Packed f32x2 FMA (Blackwell): d.lo += a.lo*b.lo ; d.hi += a.hi*b.hi
// ---------------------------------------------------------------------------
__device__ __forceinline__ void ffma2(ull& d, ull a, ull b) {
    asm volatile("fma.rn.f32x2 %0, %1, %2, %0;" : "+l"(d) : "l"(a), "l"(b));
}

__device__ __forceinline__ float2 u2f2(ull v) {
    float2 f;
    f.x = __uint_as_float((unsigned)(v & 0xffffffffull));
    f.y = __uint_as_float((unsigned)(v >> 32));
    return f;
}

__device__ __forceinline__ float4 ldcg4(const float* p) {
    float4 v;
    asm volatile("ld.global.cg.v4.f32 {%0,%1,%2,%3}, [%4];"
                 : "=f"(v.x), "=f"(v.y), "=f"(v.z), "=f"(v.w) : "l"(p));
    return v;
}

// ---------------------------------------------------------------------------
// Problem constants (shapes fixed by the dataset)
// ---------------------------------------------------------------------------
#define UDIM 1024
#define BATCH 32
#define TDIM 2048
#define CH 16                 // chunk length
#define NCH (TDIM / CH)       // 128 chunks

// ---------------------------------------------------------------------------
// Scratch (device globals; no runtime allocation allowed)
// ---------------------------------------------------------------------------
__device__ float g_ubufA[NCH * BATCH * UDIM];   // 16MB Horner ping
__device__ float g_ubufB[NCH * BATCH * UDIM];   // 16MB Horner pong
__device__ float g_gbuf [NCH * BATCH * UDIM];   // 16MB chunk carries g_c
__device__ float g_RCa  [UDIM * UDIM];          // 4MB R-power ping
__device__ float g_RCb  [UDIM * UDIM];          // 4MB R-power pong

#define MAX_BAR 2048
__device__ volatile unsigned g_bar[MAX_BAR];

__global__ void __launch_bounds__(256) bar_reset_kernel() {
    int i = blockIdx.x * blockDim.x + threadIdx.x;
    if (i < MAX_BAR) *(unsigned*)&g_bar[i] = 0u;
}

__global__ void __launch_bounds__(256) copy_h0_kernel(const float* __restrict__ h0,
                                                      float* __restrict__ g) {
    int i = blockIdx.x * blockDim.x + threadIdx.x;
    if (i < BATCH * UDIM) g[i] = h0[i];
}

// ---------------------------------------------------------------------------
// Kernel A: xw = x @ kernel + const  (M = B*T rows ordered (b,t))
// 128x128 tile, BK=8, 256 threads, 8x8/thread, f32x2, register-prefetch pipe.
// ---------------------------------------------------------------------------
#define G_BM 128
#define G_BN 128
#define G_BK 8

__global__ void __launch_bounds__(256) gemm_xw_kernel(
    const float* __restrict__ A,
    const float* __restrict__ Bm,
    const float* __restrict__ Cst,
    float* __restrict__ C,
    int M, int N, int K, int T)
{
    __shared__ ull   As2[G_BK][G_BM];
    __shared__ float Bs[G_BK][G_BN];

    const int tid  = threadIdx.x;
    const int tcol = tid & 15;
    const int trow = tid >> 4;

    const size_t mBase = (size_t)blockIdx.y * G_BM;
    const int    nBase = blockIdx.x * G_BN;

    const int arow  = tid >> 1;
    const int acol  = (tid & 1) * 4;
    const int brow8 = tid >> 5;
    const int bcol  = (tid & 31) * 4;

    const float* Ap = A + (mBase + arow) * (size_t)K + acol;
    const float* Bp = Bm + nBase + (size_t)brow8 * N + bcol;

    ull acc[8][4];
#pragma unroll
    for (int i = 0; i < 8; i++)
#pragma unroll
        for (int jp = 0; jp < 4; jp++) acc[i][jp] = 0ull;

    float4 a4 = *(const float4*)Ap;
    float4 b4 = *(const float4*)Bp;

    for (int k0 = 0; k0 < K; k0 += G_BK) {
        {
            ull d;
            d = (ull)__float_as_uint(a4.x); As2[acol + 0][arow] = d | (d << 32);
            d = (ull)__float_as_uint(a4.y); As2[acol + 1][arow] = d | (d << 32);
            d = (ull)__float_as_uint(a4.z); As2[acol + 2][arow] = d | (d << 32);
            d = (ull)__float_as_uint(a4.w); As2[acol + 3][arow] = d | (d << 32);
        }
        *(float4*)&Bs[brow8][bcol] = b4;
        __syncthreads();

        if (k0 + G_BK < K) {
            a4 = *(const float4*)(Ap + k0 + G_BK);
            b4 = *(const float4*)(Bp + (size_t)(k0 + G_BK) * N);
        }

#pragma unroll
        for (int kk = 0; kk < G_BK; kk++) {
            ull a[8];
            {
                ulonglong2 t0 = *(const ulonglong2*)&As2[kk][trow * 8 + 0];
                ulonglong2 t1 = *(const ulonglong2*)&As2[kk][trow * 8 + 2];
                ulonglong2 t2 = *(const ulonglong2*)&As2[kk][trow * 8 + 4];
                ulonglong2 t3 = *(const ulonglong2*)&As2[kk][trow * 8 + 6];
                a[0] = t0.x; a[1] = t0.y; a[2] = t1.x; a[3] = t1.y;
                a[4] = t2.x; a[5] = t2.y; a[6] = t3.x; a[7] = t3.y;
            }
            ull b[4];
            {
                ulonglong2 u0 = *(const ulonglong2*)&Bs[kk][tcol * 8 + 0];
                ulonglong2 u1 = *(const ulonglong2*)&Bs[kk][tcol * 8 + 4];
                b[0] = u0.x; b[1] = u0.y; b[2] = u1.x; b[3] = u1.y;
            }
#pragma unroll
            for (int i = 0; i < 8; i++)
#pragma unroll
                for (int jp = 0; jp < 4; jp++)
                    ffma2(acc[i][jp], a[i], b[jp]);
        }
        __syncthreads();
    }

    const int bidx = (int)(mBase / (size_t)T);   // G_BM divides T
    const float* cb0 = Cst + (size_t)bidx * N + nBase + tcol * 8;
#pragma unroll
    for (int i = 0; i < 8; i++) {
        size_t row = mBase + (size_t)(trow * 8 + i);
        float* cp = C + row * (size_t)N + nBase + tcol * 8;
        float4 c0 = *(const float4*)cb0;
        float4 c1 = *(const float4*)(cb0 + 4);
        float2 q0 = u2f2(acc[i][0]);
        float2 q1 = u2f2(acc[i][1]);
        float2 q2 = u2f2(acc[i][2]);
        float2 q3 = u2f2(acc[i][3]);
        c0.x += q0.x; c0.y += q0.y; c0.z += q1.x; c0.w += q1.y;
        c1.x += q2.x; c1.y += q2.y; c1.z += q3.x; c1.w += q3.y;
        *(float4*)cp       = c0;
        *(float4*)(cp + 4) = c1;
    }
}

// ---------------------------------------------------------------------------
// Kernel B: generalized GEMM with 2-level row addressing.
//   row m -> base + (m & 31)*sB + (m >> 5)*sC     (m = chunk*32 + batch)
//   O[m] = A[m] @ Bm (+ Add[m] if Addb != null)
// Used for Horner (phase 1), chunk replay (phase 3), and R-power squarings.
// ---------------------------------------------------------------------------
__global__ void __launch_bounds__(256) gemm_rec_kernel(
    const float* __restrict__ Abase, ll AsB, ll AsC,
    const float* __restrict__ Bm,
    const float* __restrict__ Addb, ll DsB, ll DsC,
    float* __restrict__ Obase, ll OsB, ll OsC,
    int N, int K)
{
    __shared__ ull   As2[G_BK][G_BM];
    __shared__ float Bs[G_BK][G_BN];

    const int tid  = threadIdx.x;
    const int tcol = tid & 15;
    const int trow = tid >> 4;

    const ll  mBase = (ll)blockIdx.y * G_BM;
    const int nBase = blockIdx.x * G_BN;

    const int arow  = tid >> 1;
    const int acol  = (tid & 1) * 4;
    const int brow8 = tid >> 5;
    const int bcol  = (tid & 31) * 4;

    ll mA = mBase + arow;
    const float* Ap = Abase + (mA & 31) * AsB + (mA >> 5) * AsC + acol;
    const float* Bp = Bm + nBase + (size_t)brow8 * N + bcol;

    ull acc[8][4];
#pragma unroll
    for (int i = 0; i < 8; i++)
#pragma unroll
        for (int jp = 0; jp < 4; jp++) acc[i][jp] = 0ull;

    float4 a4 = *(const float4*)Ap;
    float4 b4 = *(const float4*)Bp;

    for (int k0 = 0; k0 < K; k0 += G_BK) {
        {
            ull d;
            d = (ull)__float_as_uint(a4.x); As2[acol + 0][arow] = d | (d << 32);
            d = (ull)__float_as_uint(a4.y); As2[acol + 1][arow] = d | (d << 32);
            d = (ull)__float_as_uint(a4.z); As2[acol + 2][arow] = d | (d << 32);
            d = (ull)__float_as_uint(a4.w); As2[acol + 3][arow] = d | (d << 32);
        }
        *(float4*)&Bs[brow8][bcol] = b4;
        __syncthreads();

        if (k0 + G_BK < K) {
            a4 = *(const float4*)(Ap + k0 + G_BK);
            b4 = *(const float4*)(Bp + (size_t)(k0 + G_BK) * N);
        }

#pragma unroll
        for (int kk = 0; kk < G_BK; kk++) {
            ull a[8];
            {
                ulonglong2 t0 = *(const ulonglong2*)&As2[kk][trow * 8 + 0];
                ulonglong2 t1 = *(const ulonglong2*)&As2[kk][trow * 8 + 2];
                ulonglong2 t2 = *(const ulonglong2*)&As2[kk][trow * 8 + 4];
                ulonglong2 t3 = *(const ulonglong2*)&As2[kk][trow * 8 + 6];
                a[0] = t0.x; a[1] = t0.y; a[2] = t1.x; a[3] = t1.y;
                a[4] = t2.x; a[5] = t2.y; a[6] = t3.x; a[7] = t3.y;
            }
            ull b[4];
            {
                ulonglong2 u0 = *(const ulonglong2*)&Bs[kk][tcol * 8 + 0];
                ulonglong2 u1 = *(const ulonglong2*)&Bs[kk][tcol * 8 + 4];
                b[0] = u0.x; b[1] = u0.y; b[2] = u1.x; b[3] = u1.y;
            }
#pragma unroll
            for (int i = 0; i < 8; i++)
#pragma unroll
                for (int jp = 0; jp < 4; jp++)
                    ffma2(acc[i][jp], a[i], b[jp]);
        }
        __syncthreads();
    }

#pragma unroll
    for (int i = 0; i < 8; i++) {
        ll m = mBase + trow * 8 + i;
        ll roff = (m & 31) * OsB + (m >> 5) * OsC;
        float* op = Obase + roff + nBase + tcol * 8;

        float2 q0 = u2f2(acc[i][0]);
        float2 q1 = u2f2(acc[i][1]);
        float2 q2 = u2f2(acc[i][2]);
        float2 q3 = u2f2(acc[i][3]);
        float4 c0 = make_float4(q0.x, q0.y, q1.x, q1.y);
        float4 c1 = make_float4(q2.x, q2.y, q3.x, q3.y);

        if (Addb) {
            const float* dp = Addb + (m & 31) * DsB + (m >> 5) * DsC + nBase + tcol * 8;
            float4 d0 = *(const float4*)dp;
            float4 d1 = *(const float4*)(dp + 4);
            c0.x += d0.x; c0.y += d0.y; c0.z += d0.z; c0.w += d0.w;
            c1.x += d1.x; c1.y += d1.y; c1.z += d1.z; c1.w += d1.w;
        }
        *(float4*)op       = c0;
        *(float4*)(op + 4) = c1;
    }
}

// ---------------------------------------------------------------------------
// Kernel C: phase-2 carry chain (persistent, 128 CTAs, SMEM-resident tiles).
//   g[c+1] = g[c] @ RC + u[c],  c = 0..steps-1
// CTA (bg, cg): batches [8bg, 8bg+8), columns [32cg, 32cg+32).
// SMEM: RC column-slice transposed [32][1028] (~128KB, loaded once) +
//       h slice [8][1032] (~33KB, bulk .cg load per step).
// Warp = one batch row; lane = one column. h reads are warp-broadcast LDS.
// ---------------------------------------------------------------------------
#define P2_RPAD 1028
#define P2_HPAD 1032
#define P2_HS_OFF (32 * P2_RPAD)
#define P2_SMEM_FLOATS (32 * P2_RPAD + 8 * P2_HPAD)
#define P2_CTAS 128

__global__ void __launch_bounds__(256) phase2_kernel(
    const float* __restrict__ RC,   // R^CH, (U,U)
    const float* __restrict__ u,    // (NCH, B, U) carry contributions s_c
    float* __restrict__ g,          // (NCH, B, U), g[0] preloaded with h0
    int steps)
{
    extern __shared__ float sm[];

    const int tid  = threadIdx.x;
    const int cg   = blockIdx.x & 31;
    const int bg   = blockIdx.x >> 5;
    const int col0 = cg * 32;
    const int b0   = bg * 8;

    // Load RC[:, col0:col0+32] transposed (once).
    for (int idx = tid; idx < 32 * 1024; idx += 256) {
        int j = idx & 31;
        int k = idx >> 5;
        sm[j * P2_RPAD + k] = RC[(size_t)k * UDIM + col0 + j];
    }
    __syncthreads();

    const int j = tid & 31;   // column lane
    const int b = tid >> 5;   // batch warp (0..7)
    const float* Rrow = &sm[j * P2_RPAD];
    const float* hrow = &sm[P2_HS_OFF + b * P2_HPAD];

    const unsigned P = gridDim.x;

    for (int c = 0; c < steps; c++) {
        // Bulk-load h slice g[c][b0..b0+8][:] into smem (.cg: cross-CTA data).
        const float* gsrc = g + (size_t)c * (BATCH * UDIM);
        for (int i = tid; i < 2048; i += 256) {
            int bb = i >> 8;
            int kk = (i & 255) * 4;
            float4 v = ldcg4(gsrc + (size_t)(b0 + bb) * UDIM + kk);
            *(float4*)&sm[P2_HS_OFF + bb * P2_HPAD + kk] = v;
        }
        __syncthreads();

        ull a0 = 0ull, a1 = 0ull, a2 = 0ull, a3 = 0ull;
#pragma unroll 4
        for (int k = 0; k < 1024; k += 8) {
            ulonglong2 h01 = *(const ulonglong2*)(hrow + k);
            ulonglong2 h23 = *(const ulonglong2*)(hrow + k + 4);
            ulonglong2 r01 = *(const ulonglong2*)(Rrow + k);
            ulonglong2 r23 = *(const ulonglong2*)(Rrow + k + 4);
            ffma2(a0, h01.x, r01.x);
            ffma2(a1, h01.y, r01.y);
            ffma2(a2, h23.x, r23.x);
            ffma2(a3, h23.y, r23.y);
        }
        float2 f0 = u2f2(a0), f1 = u2f2(a1), f2 = u2f2(a2), f3 = u2f2(a3);
        float sum = ((f0.x + f0.y) + (f1.x + f1.y)) +
                    ((f2.x + f2.y) + (f3.x + f3.y));

        size_t eoff = (size_t)(b0 + b) * UDIM + col0 + j;
        float v = sum + __ldg(u + (size_t)c * (BATCH * UDIM) + eoff);
        g[(size_t)(c + 1) * (BATCH * UDIM) + eoff] = v;

        // Grid barrier (per-step counter, zeroed each replay by bar_reset).
        __threadfence();
        __syncthreads();
        if (tid == 0) {
            unsigned arrived = atomicAdd((unsigned*)&g_bar[c], 1u) + 1u;
            if (arrived < P) {
                while (g_bar[c] < P) __nanosleep(64);
            }
            __threadfence();
        }
        __syncthreads();
    }
}

// ---------------------------------------------------------------------------
// Launch: inputs x, h0, const, kernel, recurrent_kernel (metadata order).
// ---------------------------------------------------------------------------
extern "C" void kernel_launch(void* const* d_in, const int* in_sizes, int n_in,
                              void* d_out, int out_size)
{
    const float* x    = (const float*)d_in[0];
    const float* h0   = (const float*)d_in[1];
    const float* cst  = (const float*)d_in[2];
    const float* kern = (const float*)d_in[3];
    const float* rker = (const float*)d_in[4];
    float* out = (float*)d_out;

    const int U = UDIM, D = UDIM, T = TDIM, B = BATCH;
    const int M = B * T;
    const ll TU = (ll)T * U;        // out row stride per batch
    const ll CU = (ll)CH * U;       // out row stride per chunk
    const ll uB = (ll)U;            // scratch strides: (chunk, batch, U)
    const ll uC = (ll)BATCH * U;

    float *ubufA, *ubufB, *gbuf, *RCa, *RCb;
    cudaGetSymbolAddress((void**)&ubufA, g_ubufA);
    cudaGetSymbolAddress((void**)&ubufB, g_ubufB);
    cudaGetSymbolAddress((void**)&gbuf,  g_gbuf);
    cudaGetSymbolAddress((void**)&RCa,   g_RCa);
    cudaGetSymbolAddress((void**)&RCb,   g_RCb);

    cudaFuncSetAttribute(phase2_kernel,
                         cudaFuncAttributeMaxDynamicSharedMemorySize,
                         P2_SMEM_FLOATS * 4);

    // 0) barrier counters
    bar_reset_kernel<<<(MAX_BAR + 255) / 256, 256>>>();

    // 1) xw = x @ kernel + const  -> out
    {
        dim3 g1(U / G_BN, M / G_BM);
        gemm_xw_kernel<<<g1, 256>>>(x, kern, cst, out, M, U, D, T);
    }

    // 2) R^16 via 4 squarings: R2->RCa, R4->RCb, R8->RCa, R16->RCb
    {
        dim3 gs(U / G_BN, U / G_BM);
        gemm_rec_kernel<<<gs, 256>>>(rker, uB, uC, rker, nullptr, 0, 0,
                                     RCa, uB, uC, U, U);
        gemm_rec_kernel<<<gs, 256>>>(RCa, uB, uC, RCa, nullptr, 0, 0,
                                     RCb, uB, uC, U, U);
        gemm_rec_kernel<<<gs, 256>>>(RCb, uB, uC, RCb, nullptr, 0, 0,
                                     RCa, uB, uC, U, U);
        gemm_rec_kernel<<<gs, 256>>>(RCa, uB, uC, RCa, nullptr, 0, 0,
                                     RCb, uB, uC, U, U);
    }

    // 3) g[0] = h0
    copy_h0_kernel<<<(B * U + 255) / 256, 256>>>(h0, gbuf);

    // 4) Phase 1 — Horner carry contributions, all chunks in parallel.
    //    u_1 = xw_{cC} @ R + xw_{cC+1}; u_j = u_{j-1} @ R + xw_{cC+j}
    {
        dim3 gp(U / G_BN, (NCH * B) / G_BM);   // M = 4096 -> 256 CTAs
        for (int jj = 1; jj < CH; jj++) {
            float* ucur = (jj & 1) ? ubufA : ubufB;
            const float* addb = out + (size_t)jj * U;
            if (jj == 1) {
                gemm_rec_kernel<<<gp, 256>>>(out, TU, CU, rker,
                                             addb, TU, CU,
                                             ucur, uB, uC, U, U);
            } else {
                const float* uprev = (jj & 1) ? ubufB : ubufA;
                gemm_rec_kernel<<<gp, 256>>>(uprev, uB, uC, rker,
                                             addb, TU, CU,
                                             ucur, uB, uC, U, U);
            }
        }
        // final s_c lands in ubufA (jj = 15, odd)
    }

    // 5) Phase 2 — serial carry chain: g[c+1] = g[c] @ R^16 + s_c
    phase2_kernel<<<P2_CTAS, 256, P2_SMEM_FLOATS * 4>>>(RCb, ubufA, gbuf,
                                                        NCH - 1);

    // 6) Phase 3 — replay recurrence inside all chunks in parallel, in place.
    //    h_{cC+j} = h_{cC+j-1} @ R + xw_{cC+j}   (h_{cC-1} = g_c)
    {
        dim3 gp(U / G_BN, (NCH * B) / G_BM);
        for (int jj = 0; jj < CH; jj++) {
            const float* addb = out + (size_t)jj * U;
            float* ob = out + (size_t)jj * U;
            if (jj == 0) {
                gemm_rec_kernel<<<gp, 256>>>(gbuf, uB, uC, rker,
                                             addb, TU, CU,
                                             ob, TU, CU, U, U);
            } else {
                const float* aprev = out + (size_t)(jj - 1) * U;
                gemm_rec_kernel<<<gp, 256>>>(aprev, TU, CU, rker,
                                             addb, TU, CU,
                                             ob, TU, CU, U, U);
            }
        }
    }
}

// round 3
// speedup vs baseline: 3.5024x; 1.0002x over previous
#include <cuda_runtime.h>
#include <cstdint>

typedef unsigned long long ull;
typedef long long ll;

// ---------------------------------------------------------------------------
// Packed f32x2 FMA (Blackwell): d.lo += a.lo*b.lo ; d.hi += a.hi*b.hi
// ---------------------------------------------------------------------------
__device__ __forceinline__ void ffma2(ull& d, ull a, ull b) {
    asm volatile("fma.rn.f32x2 %0, %1, %2, %0;" : "+l"(d) : "l"(a), "l"(b));
}

__device__ __forceinline__ float2 u2f2(ull v) {
    float2 f;
    f.x = __uint_as_float((unsigned)(v & 0xffffffffull));
    f.y = __uint_as_float((unsigned)(v >> 32));
    return f;
}

__device__ __forceinline__ float4 ldcg4(const float* p) {
    float4 v;
    asm volatile("ld.global.cg.v4.f32 {%0,%1,%2,%3}, [%4];"
                 : "=f"(v.x), "=f"(v.y), "=f"(v.z), "=f"(v.w) : "l"(p));
    return v;
}

// ---------------------------------------------------------------------------
// Problem constants (shapes fixed by the dataset)
// ---------------------------------------------------------------------------
#define UDIM 1024
#define BATCH 32
#define TDIM 2048
#define CH 16                 // chunk length
#define NCH (TDIM / CH)       // 128 chunks

// ---------------------------------------------------------------------------
// Scratch (device globals; no runtime allocation allowed)
// ---------------------------------------------------------------------------
__device__ float g_ubufA[NCH * BATCH * UDIM];   // 16MB Horner ping
__device__ float g_ubufB[NCH * BATCH * UDIM];   // 16MB Horner pong
__device__ float g_gbuf [NCH * BATCH * UDIM];   // 16MB chunk carries g_c
__device__ float g_RCa  [UDIM * UDIM];          // 4MB R-power ping
__device__ float g_RCb  [UDIM * UDIM];          // 4MB R-power pong

#define MAX_BAR 2048
__device__ volatile unsigned g_bar[MAX_BAR];

__global__ void __launch_bounds__(256) bar_reset_kernel() {
    int i = blockIdx.x * blockDim.x + threadIdx.x;
    if (i < MAX_BAR) *(unsigned*)&g_bar[i] = 0u;
}

__global__ void __launch_bounds__(256) copy_h0_kernel(const float* __restrict__ h0,
                                                      float* __restrict__ g) {
    int i = blockIdx.x * blockDim.x + threadIdx.x;
    if (i < BATCH * UDIM) g[i] = h0[i];
}

// ---------------------------------------------------------------------------
// Kernel A: xw = x @ kernel + const  (M = B*T rows ordered (b,t))
// 128x128 tile, BK=8, 256 threads, 8x8/thread, f32x2, register-prefetch pipe.
// ---------------------------------------------------------------------------
#define G_BM 128
#define G_BN 128
#define G_BK 8

__global__ void __launch_bounds__(256) gemm_xw_kernel(
    const float* __restrict__ A,
    const float* __restrict__ Bm,
    const float* __restrict__ Cst,
    float* __restrict__ C,
    int M, int N, int K, int T)
{
    __shared__ ull   As2[G_BK][G_BM];
    __shared__ float Bs[G_BK][G_BN];

    const int tid  = threadIdx.x;
    const int tcol = tid & 15;
    const int trow = tid >> 4;

    const size_t mBase = (size_t)blockIdx.y * G_BM;
    const int    nBase = blockIdx.x * G_BN;

    const int arow  = tid >> 1;
    const int acol  = (tid & 1) * 4;
    const int brow8 = tid >> 5;
    const int bcol  = (tid & 31) * 4;

    const float* Ap = A + (mBase + arow) * (size_t)K + acol;
    const float* Bp = Bm + nBase + (size_t)brow8 * N + bcol;

    ull acc[8][4];
#pragma unroll
    for (int i = 0; i < 8; i++)
#pragma unroll
        for (int jp = 0; jp < 4; jp++) acc[i][jp] = 0ull;

    float4 a4 = *(const float4*)Ap;
    float4 b4 = *(const float4*)Bp;

    for (int k0 = 0; k0 < K; k0 += G_BK) {
        {
            ull d;
            d = (ull)__float_as_uint(a4.x); As2[acol + 0][arow] = d | (d << 32);
            d = (ull)__float_as_uint(a4.y); As2[acol + 1][arow] = d | (d << 32);
            d = (ull)__float_as_uint(a4.z); As2[acol + 2][arow] = d | (d << 32);
            d = (ull)__float_as_uint(a4.w); As2[acol + 3][arow] = d | (d << 32);
        }
        *(float4*)&Bs[brow8][bcol] = b4;
        __syncthreads();

        if (k0 + G_BK < K) {
            a4 = *(const float4*)(Ap + k0 + G_BK);
            b4 = *(const float4*)(Bp + (size_t)(k0 + G_BK) * N);
        }

#pragma unroll
        for (int kk = 0; kk < G_BK; kk++) {
            ull a[8];
            {
                ulonglong2 t0 = *(const ulonglong2*)&As2[kk][trow * 8 + 0];
                ulonglong2 t1 = *(const ulonglong2*)&As2[kk][trow * 8 + 2];
                ulonglong2 t2 = *(const ulonglong2*)&As2[kk][trow * 8 + 4];
                ulonglong2 t3 = *(const ulonglong2*)&As2[kk][trow * 8 + 6];
                a[0] = t0.x; a[1] = t0.y; a[2] = t1.x; a[3] = t1.y;
                a[4] = t2.x; a[5] = t2.y; a[6] = t3.x; a[7] = t3.y;
            }
            ull b[4];
            {
                ulonglong2 u0 = *(const ulonglong2*)&Bs[kk][tcol * 8 + 0];
                ulonglong2 u1 = *(const ulonglong2*)&Bs[kk][tcol * 8 + 4];
                b[0] = u0.x; b[1] = u0.y; b[2] = u1.x; b[3] = u1.y;
            }
#pragma unroll
            for (int i = 0; i < 8; i++)
#pragma unroll
                for (int jp = 0; jp < 4; jp++)
                    ffma2(acc[i][jp], a[i], b[jp]);
        }
        __syncthreads();
    }

    const int bidx = (int)(mBase / (size_t)T);   // G_BM divides T
    const float* cb0 = Cst + (size_t)bidx * N + nBase + tcol * 8;
#pragma unroll
    for (int i = 0; i < 8; i++) {
        size_t row = mBase + (size_t)(trow * 8 + i);
        float* cp = C + row * (size_t)N + nBase + tcol * 8;
        float4 c0 = *(const float4*)cb0;
        float4 c1 = *(const float4*)(cb0 + 4);
        float2 q0 = u2f2(acc[i][0]);
        float2 q1 = u2f2(acc[i][1]);
        float2 q2 = u2f2(acc[i][2]);
        float2 q3 = u2f2(acc[i][3]);
        c0.x += q0.x; c0.y += q0.y; c0.z += q1.x; c0.w += q1.y;
        c1.x += q2.x; c1.y += q2.y; c1.z += q3.x; c1.w += q3.y;
        *(float4*)cp       = c0;
        *(float4*)(cp + 4) = c1;
    }
}

// ---------------------------------------------------------------------------
// Kernel B: generalized GEMM with 2-level row addressing.
//   row m -> base + (m & 31)*sB + (m >> 5)*sC     (m = chunk*32 + batch)
//   O[m] = A[m] @ Bm (+ Add[m] if Addb != null)
// Used for Horner (phase 1), chunk replay (phase 3), and R-power squarings.
// ---------------------------------------------------------------------------
__global__ void __launch_bounds__(256) gemm_rec_kernel(
    const float* __restrict__ Abase, ll AsB, ll AsC,
    const float* __restrict__ Bm,
    const float* __restrict__ Addb, ll DsB, ll DsC,
    float* __restrict__ Obase, ll OsB, ll OsC,
    int N, int K)
{
    __shared__ ull   As2[G_BK][G_BM];
    __shared__ float Bs[G_BK][G_BN];

    const int tid  = threadIdx.x;
    const int tcol = tid & 15;
    const int trow = tid >> 4;

    const ll  mBase = (ll)blockIdx.y * G_BM;
    const int nBase = blockIdx.x * G_BN;

    const int arow  = tid >> 1;
    const int acol  = (tid & 1) * 4;
    const int brow8 = tid >> 5;
    const int bcol  = (tid & 31) * 4;

    ll mA = mBase + arow;
    const float* Ap = Abase + (mA & 31) * AsB + (mA >> 5) * AsC + acol;
    const float* Bp = Bm + nBase + (size_t)brow8 * N + bcol;

    ull acc[8][4];
#pragma unroll
    for (int i = 0; i < 8; i++)
#pragma unroll
        for (int jp = 0; jp < 4; jp++) acc[i][jp] = 0ull;

    float4 a4 = *(const float4*)Ap;
    float4 b4 = *(const float4*)Bp;

    for (int k0 = 0; k0 < K; k0 += G_BK) {
        {
            ull d;
            d = (ull)__float_as_uint(a4.x); As2[acol + 0][arow] = d | (d << 32);
            d = (ull)__float_as_uint(a4.y); As2[acol + 1][arow] = d | (d << 32);
            d = (ull)__float_as_uint(a4.z); As2[acol + 2][arow] = d | (d << 32);
            d = (ull)__float_as_uint(a4.w); As2[acol + 3][arow] = d | (d << 32);
        }
        *(float4*)&Bs[brow8][bcol] = b4;
        __syncthreads();

        if (k0 + G_BK < K) {
            a4 = *(const float4*)(Ap + k0 + G_BK);
            b4 = *(const float4*)(Bp + (size_t)(k0 + G_BK) * N);
        }

#pragma unroll
        for (int kk = 0; kk < G_BK; kk++) {
            ull a[8];
            {
                ulonglong2 t0 = *(const ulonglong2*)&As2[kk][trow * 8 + 0];
                ulonglong2 t1 = *(const ulonglong2*)&As2[kk][trow * 8 + 2];
                ulonglong2 t2 = *(const ulonglong2*)&As2[kk][trow * 8 + 4];
                ulonglong2 t3 = *(const ulonglong2*)&As2[kk][trow * 8 + 6];
                a[0] = t0.x; a[1] = t0.y; a[2] = t1.x; a[3] = t1.y;
                a[4] = t2.x; a[5] = t2.y; a[6] = t3.x; a[7] = t3.y;
            }
            ull b[4];
            {
                ulonglong2 u0 = *(const ulonglong2*)&Bs[kk][tcol * 8 + 0];
                ulonglong2 u1 = *(const ulonglong2*)&Bs[kk][tcol * 8 + 4];
                b[0] = u0.x; b[1] = u0.y; b[2] = u1.x; b[3] = u1.y;
            }
#pragma unroll
            for (int i = 0; i < 8; i++)
#pragma unroll
                for (int jp = 0; jp < 4; jp++)
                    ffma2(acc[i][jp], a[i], b[jp]);
        }
        __syncthreads();
    }

#pragma unroll
    for (int i = 0; i < 8; i++) {
        ll m = mBase + trow * 8 + i;
        ll roff = (m & 31) * OsB + (m >> 5) * OsC;
        float* op = Obase + roff + nBase + tcol * 8;

        float2 q0 = u2f2(acc[i][0]);
        float2 q1 = u2f2(acc[i][1]);
        float2 q2 = u2f2(acc[i][2]);
        float2 q3 = u2f2(acc[i][3]);
        float4 c0 = make_float4(q0.x, q0.y, q1.x, q1.y);
        float4 c1 = make_float4(q2.x, q2.y, q3.x, q3.y);

        if (Addb) {
            const float* dp = Addb + (m & 31) * DsB + (m >> 5) * DsC + nBase + tcol * 8;
            float4 d0 = *(const float4*)dp;
            float4 d1 = *(const float4*)(dp + 4);
            c0.x += d0.x; c0.y += d0.y; c0.z += d0.z; c0.w += d0.w;
            c1.x += d1.x; c1.y += d1.y; c1.z += d1.z; c1.w += d1.w;
        }
        *(float4*)op       = c0;
        *(float4*)(op + 4) = c1;
    }
}

// ---------------------------------------------------------------------------
// Kernel C: phase-2 carry chain (persistent, 128 CTAs, SMEM-resident tiles).
//   g[c+1] = g[c] @ RC + u[c],  c = 0..steps-1
// CTA (bg, cg): batches [8bg, 8bg+8), columns [32cg, 32cg+32).
// SMEM: RC column-slice transposed [32][1028] (~128KB, loaded once) +
//       h slice [8][1032] (~33KB, bulk .cg load per step).
// Warp = one batch row; lane = one column. h reads are warp-broadcast LDS.
// ---------------------------------------------------------------------------
#define P2_RPAD 1028
#define P2_HPAD 1032
#define P2_HS_OFF (32 * P2_RPAD)
#define P2_SMEM_FLOATS (32 * P2_RPAD + 8 * P2_HPAD)
#define P2_CTAS 128

__global__ void __launch_bounds__(256) phase2_kernel(
    const float* __restrict__ RC,   // R^CH, (U,U)
    const float* __restrict__ u,    // (NCH, B, U) carry contributions s_c
    float* __restrict__ g,          // (NCH, B, U), g[0] preloaded with h0
    int steps)
{
    extern __shared__ float sm[];

    const int tid  = threadIdx.x;
    const int cg   = blockIdx.x & 31;
    const int bg   = blockIdx.x >> 5;
    const int col0 = cg * 32;
    const int b0   = bg * 8;

    // Load RC[:, col0:col0+32] transposed (once).
    for (int idx = tid; idx < 32 * 1024; idx += 256) {
        int j = idx & 31;
        int k = idx >> 5;
        sm[j * P2_RPAD + k] = RC[(size_t)k * UDIM + col0 + j];
    }
    __syncthreads();

    const int j = tid & 31;   // column lane
    const int b = tid >> 5;   // batch warp (0..7)
    const float* Rrow = &sm[j * P2_RPAD];
    const float* hrow = &sm[P2_HS_OFF + b * P2_HPAD];

    const unsigned P = gridDim.x;

    for (int c = 0; c < steps; c++) {
        // Bulk-load h slice g[c][b0..b0+8][:] into smem (.cg: cross-CTA data).
        const float* gsrc = g + (size_t)c * (BATCH * UDIM);
        for (int i = tid; i < 2048; i += 256) {
            int bb = i >> 8;
            int kk = (i & 255) * 4;
            float4 v = ldcg4(gsrc + (size_t)(b0 + bb) * UDIM + kk);
            *(float4*)&sm[P2_HS_OFF + bb * P2_HPAD + kk] = v;
        }
        __syncthreads();

        ull a0 = 0ull, a1 = 0ull, a2 = 0ull, a3 = 0ull;
#pragma unroll 4
        for (int k = 0; k < 1024; k += 8) {
            ulonglong2 h01 = *(const ulonglong2*)(hrow + k);
            ulonglong2 h23 = *(const ulonglong2*)(hrow + k + 4);
            ulonglong2 r01 = *(const ulonglong2*)(Rrow + k);
            ulonglong2 r23 = *(const ulonglong2*)(Rrow + k + 4);
            ffma2(a0, h01.x, r01.x);
            ffma2(a1, h01.y, r01.y);
            ffma2(a2, h23.x, r23.x);
            ffma2(a3, h23.y, r23.y);
        }
        float2 f0 = u2f2(a0), f1 = u2f2(a1), f2 = u2f2(a2), f3 = u2f2(a3);
        float sum = ((f0.x + f0.y) + (f1.x + f1.y)) +
                    ((f2.x + f2.y) + (f3.x + f3.y));

        size_t eoff = (size_t)(b0 + b) * UDIM + col0 + j;
        float v = sum + __ldg(u + (size_t)c * (BATCH * UDIM) + eoff);
        g[(size_t)(c + 1) * (BATCH * UDIM) + eoff] = v;

        // Grid barrier (per-step counter, zeroed each replay by bar_reset).
        __threadfence();
        __syncthreads();
        if (tid == 0) {
            unsigned arrived = atomicAdd((unsigned*)&g_bar[c], 1u) + 1u;
            if (arrived < P) {
                while (g_bar[c] < P) __nanosleep(64);
            }
            __threadfence();
        }
        __syncthreads();
    }
}

// ---------------------------------------------------------------------------
// Launch: inputs x, h0, const, kernel, recurrent_kernel (metadata order).
// ---------------------------------------------------------------------------
extern "C" void kernel_launch(void* const* d_in, const int* in_sizes, int n_in,
                              void* d_out, int out_size)
{
    const float* x    = (const float*)d_in[0];
    const float* h0   = (const float*)d_in[1];
    const float* cst  = (const float*)d_in[2];
    const float* kern = (const float*)d_in[3];
    const float* rker = (const float*)d_in[4];
    float* out = (float*)d_out;

    const int U = UDIM, D = UDIM, T = TDIM, B = BATCH;
    const int M = B * T;
    const ll TU = (ll)T * U;        // out row stride per batch
    const ll CU = (ll)CH * U;       // out row stride per chunk
    const ll uB = (ll)U;            // scratch strides: (chunk, batch, U)
    const ll uC = (ll)BATCH * U;

    float *ubufA, *ubufB, *gbuf, *RCa, *RCb;
    cudaGetSymbolAddress((void**)&ubufA, g_ubufA);
    cudaGetSymbolAddress((void**)&ubufB, g_ubufB);
    cudaGetSymbolAddress((void**)&gbuf,  g_gbuf);
    cudaGetSymbolAddress((void**)&RCa,   g_RCa);
    cudaGetSymbolAddress((void**)&RCb,   g_RCb);

    cudaFuncSetAttribute(phase2_kernel,
                         cudaFuncAttributeMaxDynamicSharedMemorySize,
                         P2_SMEM_FLOATS * 4);

    // 0) barrier counters
    bar_reset_kernel<<<(MAX_BAR + 255) / 256, 256>>>();

    // 1) xw = x @ kernel + const  -> out
    {
        dim3 g1(U / G_BN, M / G_BM);
        gemm_xw_kernel<<<g1, 256>>>(x, kern, cst, out, M, U, D, T);
    }

    // 2) R^16 via 4 squarings: R2->RCa, R4->RCb, R8->RCa, R16->RCb
    {
        dim3 gs(U / G_BN, U / G_BM);
        gemm_rec_kernel<<<gs, 256>>>(rker, uB, uC, rker, nullptr, 0, 0,
                                     RCa, uB, uC, U, U);
        gemm_rec_kernel<<<gs, 256>>>(RCa, uB, uC, RCa, nullptr, 0, 0,
                                     RCb, uB, uC, U, U);
        gemm_rec_kernel<<<gs, 256>>>(RCb, uB, uC, RCb, nullptr, 0, 0,
                                     RCa, uB, uC, U, U);
        gemm_rec_kernel<<<gs, 256>>>(RCa, uB, uC, RCa, nullptr, 0, 0,
                                     RCb, uB, uC, U, U);
    }

    // 3) g[0] = h0
    copy_h0_kernel<<<(B * U + 255) / 256, 256>>>(h0, gbuf);

    // 4) Phase 1 — Horner carry contributions, all chunks in parallel.
    //    u_1 = xw_{cC} @ R + xw_{cC+1}; u_j = u_{j-1} @ R + xw_{cC+j}
    {
        dim3 gp(U / G_BN, (NCH * B) / G_BM);   // M = 4096 -> 256 CTAs
        for (int jj = 1; jj < CH; jj++) {
            float* ucur = (jj & 1) ? ubufA : ubufB;
            const float* addb = out + (size_t)jj * U;
            if (jj == 1) {
                gemm_rec_kernel<<<gp, 256>>>(out, TU, CU, rker,
                                             addb, TU, CU,
                                             ucur, uB, uC, U, U);
            } else {
                const float* uprev = (jj & 1) ? ubufB : ubufA;
                gemm_rec_kernel<<<gp, 256>>>(uprev, uB, uC, rker,
                                             addb, TU, CU,
                                             ucur, uB, uC, U, U);
            }
        }
        // final s_c lands in ubufA (jj = 15, odd)
    }

    // 5) Phase 2 — serial carry chain: g[c+1] = g[c] @ R^16 + s_c
    phase2_kernel<<<P2_CTAS, 256, P2_SMEM_FLOATS * 4>>>(RCb, ubufA, gbuf,
                                                        NCH - 1);

    // 6) Phase 3 — replay recurrence inside all chunks in parallel, in place.
    //    h_{cC+j} = h_{cC+j-1} @ R + xw_{cC+j}   (h_{cC-1} = g_c)
    {
        dim3 gp(U / G_BN, (NCH * B) / G_BM);
        for (int jj = 0; jj < CH; jj++) {
            const float* addb = out + (size_t)jj * U;
            float* ob = out + (size_t)jj * U;
            if (jj == 0) {
                gemm_rec_kernel<<<gp, 256>>>(gbuf, uB, uC, rker,
                                             addb, TU, CU,
                                             ob, TU, CU, U, U);
            } else {
                const float* aprev = out + (size_t)(jj - 1) * U;
                gemm_rec_kernel<<<gp, 256>>>(aprev, TU, CU, rker,
                                             addb, TU, CU,
                                             ob, TU, CU, U, U);
            }
        }
    }
}

// round 5
// speedup vs baseline: 10.0600x; 2.8723x over previous
#include <cuda_runtime.h>
#include <cuda_bf16.h>
#include <cstdint>

typedef unsigned long long ull;
typedef long long ll;
typedef unsigned short u16;
typedef unsigned int u32;

#define UDIM 1024
#define BATCH 32
#define TDIM 2048
#define CH 16
#define NCH (TDIM / CH)
#define KTOT 3072

// ---------------- scratch (device globals; no runtime alloc) ----------------
__device__ u16   g_Xhi[(size_t)BATCH * TDIM * UDIM];
__device__ u16   g_Xlo[(size_t)BATCH * TDIM * UDIM];
__device__ u16   g_UAhi[NCH * BATCH * UDIM], g_UAlo[NCH * BATCH * UDIM];
__device__ u16   g_UBhi[NCH * BATCH * UDIM], g_UBlo[NCH * BATCH * UDIM];
__device__ u16   g_KThi[UDIM * UDIM], g_KTlo[UDIM * UDIM];
__device__ u16   g_RThi[UDIM * UDIM], g_RTlo[UDIM * UDIM];
__device__ u16   g_SAhi[UDIM * UDIM], g_SAlo[UDIM * UDIM];
__device__ u16   g_SBhi[UDIM * UDIM], g_SBlo[UDIM * UDIM];
__device__ u16   g_TShi[UDIM * UDIM], g_TSlo[UDIM * UDIM];
__device__ float g_Wbuf[UDIM * UDIM];
__device__ float g_uF  [NCH * BATCH * UDIM];
__device__ float g_gbuf[NCH * BATCH * UDIM];

#define MAX_BAR 2048
__device__ volatile unsigned g_bar[MAX_BAR];

__global__ void __launch_bounds__(256) bar_reset_kernel() {
    int i = blockIdx.x * blockDim.x + threadIdx.x;
    if (i < MAX_BAR) *(unsigned*)&g_bar[i] = 0u;
}
__global__ void __launch_bounds__(256) copy_h0_kernel(const float* __restrict__ h0,
                                                      float* __restrict__ g) {
    int i = blockIdx.x * blockDim.x + threadIdx.x;
    if (i < BATCH * UDIM) g[i] = h0[i];
}

// ---------------- helpers ----------------
__device__ __forceinline__ u32 smem_u32(const void* p) {
    u32 a;
    asm("{ .reg .u64 t; cvta.to.shared.u64 t, %1; cvt.u32.u64 %0, t; }"
        : "=r"(a) : "l"(p));
    return a;
}
#define SWZ(o) ((o) ^ (((o) >> 3) & 0x70))

__device__ __forceinline__ void bsplit(float v, u16& h, u16& l) {
    __nv_bfloat16 bh = __float2bfloat16_rn(v);
    float r = v - __bfloat162float(bh);
    __nv_bfloat16 bl = __float2bfloat16_rn(r);
    h = __bfloat16_as_ushort(bh);
    l = __bfloat16_as_ushort(bl);
}

__device__ __forceinline__ void ldsm4(u32 addr, u32& r0, u32& r1, u32& r2, u32& r3) {
    asm volatile("ldmatrix.sync.aligned.m8n8.x4.shared.b16 {%0,%1,%2,%3}, [%4];"
                 : "=r"(r0), "=r"(r1), "=r"(r2), "=r"(r3) : "r"(addr));
}
__device__ __forceinline__ void mma16816(float* d, const u32* a, const u32* b) {
    asm volatile(
        "mma.sync.aligned.m16n8k16.row.col.f32.bf16.bf16.f32 "
        "{%0,%1,%2,%3}, {%4,%5,%6,%7}, {%8,%9}, {%0,%1,%2,%3};"
        : "+f"(d[0]), "+f"(d[1]), "+f"(d[2]), "+f"(d[3])
        : "r"(a[0]), "r"(a[1]), "r"(a[2]), "r"(a[3]), "r"(b[0]), "r"(b[1]));
}

// ------------- split_gather: fp32 strided rows -> bf16 hi/lo natural -------
__global__ void __launch_bounds__(256) split_gather_kernel(
    const float* __restrict__ src, ll sB, ll sC,
    u16* __restrict__ hi, u16* __restrict__ lo)
{
    int m = blockIdx.x;
    int k = threadIdx.x * 4;
    ll off = (ll)(m & 31) * sB + (ll)(m >> 5) * sC + k;
    float4 v = *(const float4*)(src + off);
    u16 h0, h1, h2, h3, l0, l1, l2, l3;
    bsplit(v.x, h0, l0); bsplit(v.y, h1, l1);
    bsplit(v.z, h2, l2); bsplit(v.w, h3, l3);
    ll doff = (ll)m * 1024 + k;
    *(ushort4*)(hi + doff) = make_ushort4(h0, h1, h2, h3);
    *(ushort4*)(lo + doff) = make_ushort4(l0, l1, l2, l3);
}

// ------------- transpose_split: fp32 W[k][n] -> bf16 hi/lo of W^T [n][k] ----
__global__ void __launch_bounds__(256) transpose_split_kernel(
    const float* __restrict__ src, u16* __restrict__ thi, u16* __restrict__ tlo)
{
    __shared__ float tile[32][33];
    int bx = blockIdx.x * 32;   // n
    int by = blockIdx.y * 32;   // k
    int tx = threadIdx.x & 31;
    int ty = threadIdx.x >> 5;
#pragma unroll
    for (int i = 0; i < 32; i += 8)
        tile[ty + i][tx] = src[(ll)(by + ty + i) * 1024 + bx + tx];
    __syncthreads();
#pragma unroll
    for (int i = 0; i < 32; i += 8) {
        u16 h, l;
        bsplit(tile[tx][ty + i], h, l);
        ll off = (ll)(bx + ty + i) * 1024 + (by + tx);
        thi[off] = h;
        tlo[off] = l;
    }
}

// ---------------------------------------------------------------------------
// tgemm: C[m][n] = sum_{k<1024} Af[m][k]*Bf[n][k] via bf16 split, K'=3072:
//   region0 Ahi*Bhi, region1 Alo*Bhi, region2 Ahi*Blo (per 64-wide K chunk).
// mma.sync m16n8k16 bf16, CTA 128x128, BK=64 (SW128 rows), 3-stage cp.async.
// 8 warps (4x2): each warp 32(M) x 64(N) = 2x8 mma tiles.
// Epilogue: +Add (strided/shift), fp32 out (strided), bf16 hi/lo re-split.
// ---------------------------------------------------------------------------
#define TG_STAGE 32768              // A 16KB + B 16KB
#define TG_SMEM (3 * TG_STAGE)
#define TG_NCHK (KTOT / 64)         // 48

__global__ void __launch_bounds__(256) tgemm_kernel(
    const u16* __restrict__ Ahi, const u16* __restrict__ Alo,
    const u16* __restrict__ Bhi, const u16* __restrict__ Blo,
    const float* __restrict__ Add, int adShift, ll adSB, ll adSC,
    float* __restrict__ OutF, ll ofSB, ll ofSC,
    u16* __restrict__ OBhi, u16* __restrict__ OBlo)
{
    extern __shared__ char smraw[];
    const u32 smbase = smem_u32(smraw);

    const int tid  = threadIdx.x;
    const int wid  = tid >> 5;
    const int lane = tid & 31;
    const ll mBase = (ll)blockIdx.y * 128;
    const ll nBase = (ll)blockIdx.x * 128;

    const int wm = (wid >> 1) * 32;   // warp M offset in tile
    const int wn = (wid & 1) * 64;    // warp N offset in tile

    float acc[2][8][4];
#pragma unroll
    for (int i = 0; i < 2; i++)
#pragma unroll
        for (int j = 0; j < 8; j++)
#pragma unroll
            for (int q = 0; q < 4; q++) acc[i][j][q] = 0.0f;

    // per-thread load slots: 4 x 16B for A, 4 x 16B for B per chunk
    auto load_chunk = [&](int c, int s) {
        const int reg = c >> 4;
        const u16* aptr = (reg == 1) ? Alo : Ahi;
        const u16* bptr = (reg == 2) ? Blo : Bhi;
        const ll kbase = (ll)(c & 15) * 64;
        u32 sa = smbase + (u32)s * TG_STAGE;
        u32 sb = sa + 16384;
#pragma unroll
        for (int i = 0; i < 4; i++) {
            int idx = i * 256 + tid;          // 0..1023
            int row = idx >> 3;               // 0..127
            int cc  = (idx & 7) * 16;         // byte col in 128B row
            ll  kel = kbase + (idx & 7) * 8;  // element offset
            asm volatile("cp.async.cg.shared.global [%0], [%1], 16;"
                :: "r"(sa + SWZ((u32)(row * 128 + cc))),
                   "l"((ull)(uintptr_t)(aptr + (mBase + row) * 1024 + kel)));
            asm volatile("cp.async.cg.shared.global [%0], [%1], 16;"
                :: "r"(sb + SWZ((u32)(row * 128 + cc))),
                   "l"((ull)(uintptr_t)(bptr + (nBase + row) * 1024 + kel)));
        }
        asm volatile("cp.async.commit_group;" ::: "memory");
    };

    load_chunk(0, 0);
    load_chunk(1, 1);

    // ldmatrix lane address components
    const int aRow = (lane & 15);           // + wm + i*16
    const int aKb  = (lane >> 4) * 16;      // k byte offset within 32B (k16)
    const int bRow = (lane & 7) + ((lane >> 4) << 3);  // + wn + j16*16
    const int bKb  = ((lane >> 3) & 1) * 16;

#pragma unroll 1
    for (int c = 0; c < TG_NCHK; c++) {
        if (c + 2 < TG_NCHK) {
            asm volatile("cp.async.wait_group 1;" ::: "memory");
        } else {
            asm volatile("cp.async.wait_group 0;" ::: "memory");
        }
        __syncthreads();
        if (c + 2 < TG_NCHK) load_chunk(c + 2, (c + 2) % 3);

        u32 sa = smbase + (u32)(c % 3) * TG_STAGE;
        u32 sb = sa + 16384;

#pragma unroll
        for (int k16 = 0; k16 < 4; k16++) {
            const int kb = k16 * 32;
            u32 areg[2][4];
#pragma unroll
            for (int i = 0; i < 2; i++) {
                u32 ad = sa + SWZ((u32)((wm + i * 16 + aRow) * 128 + kb + aKb));
                ldsm4(ad, areg[i][0], areg[i][1], areg[i][2], areg[i][3]);
            }
            u32 breg[4][4];
#pragma unroll
            for (int j16 = 0; j16 < 4; j16++) {
                u32 bd = sb + SWZ((u32)((wn + j16 * 16 + bRow) * 128 + kb + bKb));
                ldsm4(bd, breg[j16][0], breg[j16][1], breg[j16][2], breg[j16][3]);
            }
#pragma unroll
            for (int i = 0; i < 2; i++)
#pragma unroll
                for (int j = 0; j < 8; j++)
                    mma16816(acc[i][j], areg[i], &breg[j >> 1][(j & 1) * 2]);
        }
        __syncthreads();
    }

    // ---- epilogue: thread owns rows {wm+g, wm+g+8, wm+16+g, wm+24+g} ----
    const int g  = lane >> 2;
    const int tg = (lane & 3) * 2;

#pragma unroll
    for (int i = 0; i < 2; i++) {
#pragma unroll
        for (int half = 0; half < 2; half++) {
            ll m = mBase + wm + i * 16 + g + half * 8;
            const float* addp = Add ?
                Add + (m & ((1 << adShift) - 1)) * adSB + (m >> adShift) * adSC + nBase
                : (const float*)0;
            float* ofp = OutF ?
                OutF + (m & 31) * ofSB + (m >> 5) * ofSC + nBase : (float*)0;
            u16* obh = OBhi ? OBhi + m * 1024 + nBase : (u16*)0;
            u16* obl = OBlo ? OBlo + m * 1024 + nBase : (u16*)0;
#pragma unroll
            for (int j = 0; j < 8; j++) {
                int n = wn + j * 8 + tg;
                float v0 = acc[i][j][half * 2 + 0];
                float v1 = acc[i][j][half * 2 + 1];
                if (addp) {
                    float2 a = *(const float2*)(addp + n);
                    v0 += a.x; v1 += a.y;
                }
                if (ofp)
                    *(float2*)(ofp + n) = make_float2(v0, v1);
                if (obh) {
                    u16 h0, h1, l0, l1;
                    bsplit(v0, h0, l0);
                    bsplit(v1, h1, l1);
                    *(ushort2*)(obh + n) = make_ushort2(h0, h1);
                    *(ushort2*)(obl + n) = make_ushort2(l0, l1);
                }
            }
        }
    }
}

// ---------------------------------------------------------------------------
// phase2: serial carry chain g[c+1] = g[c] @ R^16 + u[c]  (fp32, persistent)
// ---------------------------------------------------------------------------
__device__ __forceinline__ void ffma2(ull& d, ull a, ull b) {
    asm volatile("fma.rn.f32x2 %0, %1, %2, %0;" : "+l"(d) : "l"(a), "l"(b));
}
__device__ __forceinline__ float2 u2f2(ull v) {
    float2 f;
    f.x = __uint_as_float((unsigned)(v & 0xffffffffull));
    f.y = __uint_as_float((unsigned)(v >> 32));
    return f;
}
__device__ __forceinline__ float4 ldcg4(const float* p) {
    float4 v;
    asm volatile("ld.global.cg.v4.f32 {%0,%1,%2,%3}, [%4];"
                 : "=f"(v.x), "=f"(v.y), "=f"(v.z), "=f"(v.w) : "l"(p));
    return v;
}
#define P2_RPAD 1028
#define P2_HPAD 1032
#define P2_HS_OFF (32 * P2_RPAD)
#define P2_SMEM_FLOATS (32 * P2_RPAD + 8 * P2_HPAD)
#define P2_CTAS 128

__global__ void __launch_bounds__(256) phase2_kernel(
    const float* __restrict__ RC, const float* __restrict__ u,
    float* __restrict__ g, int steps)
{
    extern __shared__ float sm[];
    const int tid = threadIdx.x;
    const int col0 = (blockIdx.x & 31) * 32;
    const int b0   = (blockIdx.x >> 5) * 8;

    for (int idx = tid; idx < 32 * 1024; idx += 256)
        sm[(idx & 31) * P2_RPAD + (idx >> 5)] =
            RC[(size_t)(idx >> 5) * UDIM + col0 + (idx & 31)];
    __syncthreads();

    const int j = tid & 31;
    const int b = tid >> 5;
    const float* Rrow = &sm[j * P2_RPAD];
    const float* hrow = &sm[P2_HS_OFF + b * P2_HPAD];
    const unsigned P = gridDim.x;

    for (int c = 0; c < steps; c++) {
        const float* gsrc = g + (size_t)c * (BATCH * UDIM);
        for (int i = tid; i < 2048; i += 256) {
            int bb = i >> 8, kk = (i & 255) * 4;
            float4 v = ldcg4(gsrc + (size_t)(b0 + bb) * UDIM + kk);
            *(float4*)&sm[P2_HS_OFF + bb * P2_HPAD + kk] = v;
        }
        __syncthreads();

        ull a0 = 0, a1 = 0, a2 = 0, a3 = 0;
#pragma unroll 4
        for (int k = 0; k < 1024; k += 8) {
            ulonglong2 h01 = *(const ulonglong2*)(hrow + k);
            ulonglong2 h23 = *(const ulonglong2*)(hrow + k + 4);
            ulonglong2 r01 = *(const ulonglong2*)(Rrow + k);
            ulonglong2 r23 = *(const ulonglong2*)(Rrow + k + 4);
            ffma2(a0, h01.x, r01.x); ffma2(a1, h01.y, r01.y);
            ffma2(a2, h23.x, r23.x); ffma2(a3, h23.y, r23.y);
        }
        float2 f0 = u2f2(a0), f1 = u2f2(a1), f2 = u2f2(a2), f3 = u2f2(a3);
        float sum = ((f0.x + f0.y) + (f1.x + f1.y)) +
                    ((f2.x + f2.y) + (f3.x + f3.y));

        size_t eoff = (size_t)(b0 + b) * UDIM + col0 + j;
        g[(size_t)(c + 1) * (BATCH * UDIM) + eoff] =
            sum + __ldg(u + (size_t)c * (BATCH * UDIM) + eoff);

        __threadfence();
        __syncthreads();
        if (tid == 0) {
            unsigned arrived = atomicAdd((unsigned*)&g_bar[c], 1u) + 1u;
            if (arrived < P)
                while (g_bar[c] < P) __nanosleep(64);
            __threadfence();
        }
        __syncthreads();
    }
}

// ---------------------------------------------------------------------------
extern "C" void kernel_launch(void* const* d_in, const int* in_sizes, int n_in,
                              void* d_out, int out_size)
{
    const float* x    = (const float*)d_in[0];
    const float* h0   = (const float*)d_in[1];
    const float* cst  = (const float*)d_in[2];
    const float* kern = (const float*)d_in[3];
    const float* rker = (const float*)d_in[4];
    float* out = (float*)d_out;

    const ll TU = (ll)TDIM * UDIM;   // out stride per batch
    const ll CU = (ll)CH * UDIM;     // out stride per chunk (16 rows)

    u16 *Xhi, *Xlo, *UAhi, *UAlo, *UBhi, *UBlo, *KThi, *KTlo, *RThi, *RTlo;
    u16 *SAhi, *SAlo, *SBhi, *SBlo, *TShi, *TSlo;
    float *Wbuf, *uF, *gbuf;
    cudaGetSymbolAddress((void**)&Xhi, g_Xhi);   cudaGetSymbolAddress((void**)&Xlo, g_Xlo);
    cudaGetSymbolAddress((void**)&UAhi, g_UAhi); cudaGetSymbolAddress((void**)&UAlo, g_UAlo);
    cudaGetSymbolAddress((void**)&UBhi, g_UBhi); cudaGetSymbolAddress((void**)&UBlo, g_UBlo);
    cudaGetSymbolAddress((void**)&KThi, g_KThi); cudaGetSymbolAddress((void**)&KTlo, g_KTlo);
    cudaGetSymbolAddress((void**)&RThi, g_RThi); cudaGetSymbolAddress((void**)&RTlo, g_RTlo);
    cudaGetSymbolAddress((void**)&SAhi, g_SAhi); cudaGetSymbolAddress((void**)&SAlo, g_SAlo);
    cudaGetSymbolAddress((void**)&SBhi, g_SBhi); cudaGetSymbolAddress((void**)&SBlo, g_SBlo);
    cudaGetSymbolAddress((void**)&TShi, g_TShi); cudaGetSymbolAddress((void**)&TSlo, g_TSlo);
    cudaGetSymbolAddress((void**)&Wbuf, g_Wbuf);
    cudaGetSymbolAddress((void**)&uF, g_uF);
    cudaGetSymbolAddress((void**)&gbuf, g_gbuf);

    cudaFuncSetAttribute(tgemm_kernel,
        cudaFuncAttributeMaxDynamicSharedMemorySize, TG_SMEM);
    cudaFuncSetAttribute(phase2_kernel,
        cudaFuncAttributeMaxDynamicSharedMemorySize, P2_SMEM_FLOATS * 4);

    bar_reset_kernel<<<(MAX_BAR + 255) / 256, 256>>>();

    // splits of inputs
    split_gather_kernel<<<BATCH * TDIM, 256>>>(x, 1024, 32768, Xhi, Xlo);
    dim3 gt(32, 32);
    transpose_split_kernel<<<gt, 256>>>(kern, KThi, KTlo);
    transpose_split_kernel<<<gt, 256>>>(rker, RThi, RTlo);
    split_gather_kernel<<<UDIM, 256>>>(rker, 1024, 32768, SAhi, SAlo);
    copy_h0_kernel<<<(BATCH * UDIM + 255) / 256, 256>>>(h0, gbuf);

    // phase 0: xw = x @ kernel + const -> out (natural rows m = b*T + t)
    {
        dim3 g0(8, 512);
        tgemm_kernel<<<g0, 256, TG_SMEM>>>(Xhi, Xlo, KThi, KTlo,
            cst, 11, 0, 1024,          // Add: const[b], b = m >> 11
            out, 1024, 32768,          // OutF natural
            nullptr, nullptr);
    }

    // R^16 via 4 tensor squarings (transpose-split between levels)
    {
        dim3 gs(8, 8);
        tgemm_kernel<<<gs, 256, TG_SMEM>>>(SAhi, SAlo, RThi, RTlo,
            nullptr, 5, 0, 0, Wbuf, 1024, 32768, SBhi, SBlo);        // R^2
        transpose_split_kernel<<<gt, 256>>>(Wbuf, TShi, TSlo);
        tgemm_kernel<<<gs, 256, TG_SMEM>>>(SBhi, SBlo, TShi, TSlo,
            nullptr, 5, 0, 0, Wbuf, 1024, 32768, SAhi, SAlo);        // R^4
        transpose_split_kernel<<<gt, 256>>>(Wbuf, TShi, TSlo);
        tgemm_kernel<<<gs, 256, TG_SMEM>>>(SAhi, SAlo, TShi, TSlo,
            nullptr, 5, 0, 0, Wbuf, 1024, 32768, SBhi, SBlo);        // R^8
        transpose_split_kernel<<<gt, 256>>>(Wbuf, TShi, TSlo);
        tgemm_kernel<<<gs, 256, TG_SMEM>>>(SBhi, SBlo, TShi, TSlo,
            nullptr, 5, 0, 0, Wbuf, 1024, 32768, nullptr, nullptr);  // R^16 fp32
    }

    // gather xw rows at t = c*16 (chunk heads), split -> UA
    split_gather_kernel<<<NCH * BATCH, 256>>>(out, TU, CU, UAhi, UAlo);

    // phase 1: Horner u_j = u_{j-1} @ R + xw_{c*16+j}, j = 1..15
    {
        dim3 gp(8, 32);
        for (int jj = 1; jj < CH; jj++) {
            const u16* ah = (jj & 1) ? UAhi : UBhi;
            const u16* al = (jj & 1) ? UAlo : UBlo;
            u16* oh = (jj & 1) ? UBhi : UAhi;
            u16* ol = (jj & 1) ? UBlo : UAlo;
            bool last = (jj == CH - 1);
            tgemm_kernel<<<gp, 256, TG_SMEM>>>(ah, al, RThi, RTlo,
                out + (size_t)jj * UDIM, 5, TU, CU,
                last ? uF : nullptr, 1024, 32768,
                last ? nullptr : oh, last ? nullptr : ol);
        }
    }

    // phase 2: g[c+1] = g[c] @ R^16 + s_c  (127 serial steps, fp32)
    phase2_kernel<<<P2_CTAS, 256, P2_SMEM_FLOATS * 4>>>(Wbuf, uF, gbuf, NCH - 1);

    // split carries -> UA
    split_gather_kernel<<<NCH * BATCH, 256>>>(gbuf, 1024, 32768, UAhi, UAlo);

    // phase 3: replay h_{c*16+j} = h_prev @ R + xw, in place into out
    {
        dim3 gp(8, 32);
        for (int jj = 0; jj < CH; jj++) {
            const u16* ah = (jj & 1) ? UBhi : UAhi;
            const u16* al = (jj & 1) ? UBlo : UAlo;
            u16* oh = (jj & 1) ? UAhi : UBhi;
            u16* ol = (jj & 1) ? UAlo : UBlo;
            bool last = (jj == CH - 1);
            tgemm_kernel<<<gp, 256, TG_SMEM>>>(ah, al, RThi, RTlo,
                out + (size_t)jj * UDIM, 5, TU, CU,
                out + (size_t)jj * UDIM, TU, CU,
                last ? nullptr : oh, last ? nullptr : ol);
        }
    }
}